// round 13
// baseline (speedup 1.0000x reference)
#include <cuda_runtime.h>
#include <math.h>

#define NN 5000
#define NL 20000
#define NP 50000

typedef unsigned long long ull;

// ------------------------- device-global scratch -------------------------
__device__ __align__(16) float g_link[2][NL * 32];
__device__ __align__(16) float g_node[2][NN * 32];
__device__ __align__(16) float g_path[NP * 64];
__device__ __align__(16) float g_m[NL * 64];
__device__ __align__(16) float g_Lx[NL * 192];
__device__ __align__(16) float g_Nx[NN * 192];
__device__ __align__(16) float g_z[(size_t)NN * 1056];
__device__ __align__(16) float g_W2[32768];
__device__ __align__(16) float g_wpack[12288];
__device__ __align__(16) float g_b1pack[192];
__device__ __align__(16) float g_We[4096];
__device__ __align__(16) float g_be[32];

// ------------------------------ helpers ----------------------------------
__device__ __forceinline__ float sigm(float x) {
    return __fdividef(1.0f, 1.0f + __expf(-x));
}
__device__ __forceinline__ float tanh_fast(float x) {
    float ax = fabsf(x);
    float e  = __expf(-2.0f * ax);
    float t  = __fdividef(1.0f - e, 1.0f + e);
    return copysignf(t, x);
}
__device__ __forceinline__ float selu_f(float x) {
    return x > 0.0f ? 1.0507009873554805f * x
                    : 1.7580993408473766f * (__expf(x) - 1.0f);
}
__device__ __forceinline__ void red4(float* a, float x, float y, float z, float w) {
    asm volatile("red.global.add.v4.f32 [%0], {%1,%2,%3,%4};"
                 :: "l"(a), "f"(x), "f"(y), "f"(z), "f"(w) : "memory");
}
__device__ __forceinline__ ull pack2(float a, float b) {
    ull r; asm("mov.b64 %0, {%1,%2};" : "=l"(r) : "f"(a), "f"(b)); return r;
}
__device__ __forceinline__ void ffma2(ull& acc, ull a, ull b) {
    asm("fma.rn.f32x2 %0, %1, %2, %0;" : "+l"(acc) : "l"(a), "l"(b));
}
__device__ __forceinline__ void unpack2(ull v, float& lo, float& hi) {
    asm("mov.b64 {%0,%1}, %2;" : "=f"(lo), "=f"(hi) : "l"(v));
}

// ------------- merged prep: gru pack | fused edge MLP | W2 permute --------
// wpack quad layout: [i][g][jg] -> contiguous 256B per (i,g) warp load
__global__ void prep_all_k(const float* __restrict__ wh, const float* __restrict__ b,
                           const float* __restrict__ w1, const float* __restrict__ b1,
                           const float* __restrict__ w2, const float* __restrict__ b2,
                           const float* __restrict__ wk) {
    int idx = blockIdx.x * 256 + threadIdx.x;
    if (idx < 12288) {
        int k = idx & 3;
        int q = idx >> 2;           // quad index = (i*3 + g)*16 + jg
        int jg = q & 15;
        int g  = (q >> 4) % 3;
        int i  = (q >> 4) / 3;
        g_wpack[idx] = wh[i * 192 + g * 64 + jg * 4 + k];
    } else if (idx < 12480) {
        int r = idx - 12288;
        int k = r & 3;
        int g = (r >> 2) % 3;
        int jg = (r >> 2) / 3;
        g_b1pack[r] = b[192 + g * 64 + jg * 4 + k];
    } else if (idx < 12480 + 4096) {
        int r = idx - 12480;
        int c = r >> 5, j = r & 31;
        float acc = 0.0f;
        #pragma unroll
        for (int k = 0; k < 32; k++) acc += w1[c * 32 + k] * w2[k * 32 + j];
        g_We[r] = acc;
    } else if (idx < 12480 + 4128) {
        int j = idx - 12480 - 4096;
        float acc = b2[j];
        #pragma unroll
        for (int k = 0; k < 32; k++) acc += b1[k] * w2[k * 32 + j];
        g_be[j] = acc;
    } else if (idx < 12480 + 4128 + 32768) {
        int r = idx - 16608;
        int o = r & 31;
        int i = (r >> 5) & 31;
        int c = r >> 10;
        g_W2[i * 1024 + c * 32 + o] = wk[r];
    }
}

// -------------- merged init: link | node | path | zero m ------------------
__global__ void init_all_k(const float* __restrict__ li,
                           const float* __restrict__ ni,
                           const float* __restrict__ pi) {
    int idx = blockIdx.x * 256 + threadIdx.x;   // 5,280,000 total
    if (idx < NL * 32) {
        int l = idx >> 5, c = idx & 31;
        g_link[0][idx] = (c == 0) ? li[l] : 0.0f;
    } else if (idx < NL * 32 + NN * 32) {
        int r = idx - NL * 32;
        int n = r >> 5, c = r & 31;
        g_node[0][r] = (c == 0) ? ni[n] : 0.0f;
    } else if (idx < NL * 32 + NN * 32 + NP * 64) {
        int r = idx - NL * 32 - NN * 32;
        int p = r >> 6, c = r & 63;
        float v = 0.0f;
        if (c == 0) v = pi[p];
        else if (c == 1) v = pi[NP + p];
        g_path[r] = v;
    } else {
        g_m[idx - 4000000] = 0.0f;
    }
}

// ------ iter-1 Lx/Nx fast path (states are rank-1: only col 0 nonzero) ----
__global__ void __launch_bounds__(192) lxnx1_kernel(const float* __restrict__ wx,
                                                    const float* __restrict__ b,
                                                    const float* __restrict__ li,
                                                    const float* __restrict__ ni) {
    int tid = threadIdx.x;
    bool is_link = (blockIdx.x < 2500);
    int base = is_link ? blockIdx.x * 8 : (blockIdx.x - 2500) * 8;
    float wj = is_link ? wx[tid] : wx[6144 + tid];
    float bj = is_link ? b[tid] : 0.0f;
    const float* init = is_link ? li : ni;
    float* dst = is_link ? g_Lx : g_Nx;
    #pragma unroll
    for (int e = 0; e < 8; e++) {
        float v = init[base + e];
        dst[(size_t)(base + e) * 192 + tid] = v * wj + bj;
    }
}

// ---------- full Lx/Nx (iter 2): blocks [0,2500) links, rest nodes --------
__global__ void __launch_bounds__(192) lxnx_kernel(const float* __restrict__ wx,
                                                   const float* __restrict__ b, int cur) {
    __shared__ float swx[6144];
    __shared__ float sst[8][33];
    int tid = threadIdx.x;
    bool is_link = (blockIdx.x < 2500);
    const float* wsrc = is_link ? wx : wx + 6144;
    for (int r = tid; r < 6144; r += 192) swx[r] = wsrc[r];
    const float* st = is_link ? g_link[cur] : g_node[cur];
    int base = is_link ? blockIdx.x * 8 : (blockIdx.x - 2500) * 8;
    for (int r = tid; r < 256; r += 192) {
        int e = r >> 5, c = r & 31;
        sst[e][c] = st[(size_t)(base + e) * 32 + c];
    }
    __syncthreads();
    int j = tid;
    float bj = is_link ? b[j] : 0.0f;
    float* dst = is_link ? g_Lx : g_Nx;
    for (int e = 0; e < 8; e++) {
        float acc = bj;
        #pragma unroll
        for (int i = 0; i < 32; i++) acc += sst[e][i] * swx[i * 192 + j];
        dst[(size_t)(base + e) * 192 + j] = acc;
    }
}

// --------------------------- fused GRU scan ------------------------------
// h stored TRANSPOSED: shh[buf][p*68 + j]; inner loop reads h as float4
// per 4-i chunk (1 wavefront each after broadcast dedup).
#define GRU_SMEM_BYTES 84736

#define GRU_SUB(i, v0, v1, v2, v3)                                           \
    {                                                                        \
        ulonglong2 wz = w2m[((i) * 3 + 0) * 16 + jg];                        \
        ulonglong2 wr = w2m[((i) * 3 + 1) * 16 + jg];                        \
        ulonglong2 wh = w2m[((i) * 3 + 2) * 16 + jg];                        \
        ull hp0 = pack2(v0, v0);                                             \
        ull hp1 = pack2(v1, v1);                                             \
        ull hp2 = pack2(v2, v2);                                             \
        ull hp3 = pack2(v3, v3);                                             \
        ffma2(a2[0][0], hp0, wz.x); ffma2(a2[0][1], hp0, wz.y);              \
        ffma2(a2[0][2], hp0, wr.x); ffma2(a2[0][3], hp0, wr.y);              \
        ffma2(a2[0][4], hp0, wh.x); ffma2(a2[0][5], hp0, wh.y);              \
        ffma2(a2[1][0], hp1, wz.x); ffma2(a2[1][1], hp1, wz.y);              \
        ffma2(a2[1][2], hp1, wr.x); ffma2(a2[1][3], hp1, wr.y);              \
        ffma2(a2[1][4], hp1, wh.x); ffma2(a2[1][5], hp1, wh.y);              \
        ffma2(a2[2][0], hp2, wz.x); ffma2(a2[2][1], hp2, wz.y);              \
        ffma2(a2[2][2], hp2, wr.x); ffma2(a2[2][3], hp2, wr.y);              \
        ffma2(a2[2][4], hp2, wh.x); ffma2(a2[2][5], hp2, wh.y);              \
        ffma2(a2[3][0], hp3, wz.x); ffma2(a2[3][1], hp3, wz.y);              \
        ffma2(a2[3][2], hp3, wr.x); ffma2(a2[3][3], hp3, wr.y);              \
        ffma2(a2[3][4], hp3, wh.x); ffma2(a2[3][5], hp3, wh.y);              \
    }

template <int SCATTER, int FIRST>
__global__ void __launch_bounds__(256, 2) gru_kernel(const int* __restrict__ l2p,
                                                     const int* __restrict__ n2p) {
    extern __shared__ float sm[];
    float4* wsm = (float4*)sm;               // 3072 quads
    float*  sb1 = sm + 12288;                // 192
    float*  shh = sm + 12480;                // 2 * 4352  ([p][68] layout)

    int tid = threadIdx.x;
    int pg = tid >> 4, jg = tid & 15;
    int pbase = blockIdx.x * 64;

    const float4* wgl = (const float4*)g_wpack;
    #pragma unroll
    for (int r = 0; r < 12; r++) wsm[r * 256 + tid] = wgl[r * 256 + tid];
    if (tid < 192) sb1[tid] = g_b1pack[tid];

    // stage h transposed: shh[p*68 + j]
    const float4* gp4 = (const float4*)g_path;
    #pragma unroll
    for (int r = 0; r < 4; r++) {
        int idx = r * 256 + tid;
        int p = idx >> 4, iq = idx & 15;
        int pglob = pbase + p; if (pglob >= NP) pglob = NP - 1;
        float4 v = gp4[(size_t)pglob * 16 + iq];
        *(float4*)(shh + p * 68 + iq * 4) = v;
    }
    __syncthreads();

    const ulonglong2* sb2 = (const ulonglong2*)sb1;
    ulonglong2 bA = sb2[jg * 3 + 0];
    ulonglong2 bB = sb2[jg * 3 + 1];
    ulonglong2 bC = sb2[jg * 3 + 2];

    int pid[4]; bool pv[4];
    #pragma unroll
    for (int pp = 0; pp < 4; pp++) {
        int pglob = pbase + pg * 4 + pp;
        pv[pp] = (pglob < NP);
        pid[pp] = pv[pp] ? pglob : NP - 1;
    }
    const int hb0 = (pg * 4 + 0) * 68;
    const int hb1 = (pg * 4 + 1) * 68;
    const int hb2 = (pg * 4 + 2) * 68;
    const int hb3 = (pg * 4 + 3) * 68;

    const float4* Lx4 = (const float4*)g_Lx;
    const float4* Nx4 = (const float4*)g_Nx;
    const ulonglong2* w2m = (const ulonglong2*)wsm;

    int hbuf = 0;
    for (int t = 0; t < 8; t++) {
        float4 gz[4], gr[4], gc[4];
        int liA[4];
        #pragma unroll
        for (int pp = 0; pp < 4; pp++) {
            int e = pid[pp] * 8 + t;
            int li = l2p[e], ni = n2p[e];
            liA[pp] = li;
            const float4* lq = Lx4 + (size_t)li * 48 + jg;
            const float4* nq = Nx4 + (size_t)ni * 48 + jg;
            float4 a0 = lq[0],  b0 = nq[0];
            float4 a1 = lq[16], b1 = nq[16];
            float4 a2q = lq[32], b2q = nq[32];
            gz[pp] = make_float4(a0.x + b0.x, a0.y + b0.y, a0.z + b0.z, a0.w + b0.w);
            gr[pp] = make_float4(a1.x + b1.x, a1.y + b1.y, a1.z + b1.z, a1.w + b1.w);
            gc[pp] = make_float4(a2q.x + b2q.x, a2q.y + b2q.y, a2q.z + b2q.z, a2q.w + b2q.w);
        }

        float* shH  = shh + hbuf * 4352;
        float* shHn = shh + (hbuf ^ 1) * 4352;

        ull a2[4][6];
        #pragma unroll
        for (int pp = 0; pp < 4; pp++) {
            a2[pp][0] = bA.x; a2[pp][1] = bA.y;
            a2[pp][2] = bB.x; a2[pp][3] = bB.y;
            a2[pp][4] = bC.x; a2[pp][5] = bC.y;
        }

        if (FIRST && t == 0) {
            // h0 has only hidden dims 0,1 nonzero — 2-term inner loop (bit-exact)
            float2 h20 = *(const float2*)(shH + hb0);
            float2 h21 = *(const float2*)(shH + hb1);
            float2 h22 = *(const float2*)(shH + hb2);
            float2 h23 = *(const float2*)(shH + hb3);
            GRU_SUB(0, h20.x, h21.x, h22.x, h23.x);
            GRU_SUB(1, h20.y, h21.y, h22.y, h23.y);
        } else {
            #pragma unroll 2
            for (int i4 = 0; i4 < 64; i4 += 4) {
                float4 h40 = *(const float4*)(shH + hb0 + i4);
                float4 h41 = *(const float4*)(shH + hb1 + i4);
                float4 h42 = *(const float4*)(shH + hb2 + i4);
                float4 h43 = *(const float4*)(shH + hb3 + i4);
                GRU_SUB(i4 + 0, h40.x, h41.x, h42.x, h43.x);
                GRU_SUB(i4 + 1, h40.y, h41.y, h42.y, h43.y);
                GRU_SUB(i4 + 2, h40.z, h41.z, h42.z, h43.z);
                GRU_SUB(i4 + 3, h40.w, h41.w, h42.w, h43.w);
            }
        }

        int j0 = jg * 4;
        #pragma unroll
        for (int pp = 0; pp < 4; pp++) {
            int p = pg * 4 + pp;
            float az0, az1, az2, az3, ar0, ar1, ar2, ar3, ah0, ah1, ah2, ah3;
            unpack2(a2[pp][0], az0, az1); unpack2(a2[pp][1], az2, az3);
            unpack2(a2[pp][2], ar0, ar1); unpack2(a2[pp][3], ar2, ar3);
            unpack2(a2[pp][4], ah0, ah1); unpack2(a2[pp][5], ah2, ah3);
            float z0 = sigm(gz[pp].x + az0);
            float z1 = sigm(gz[pp].y + az1);
            float z2 = sigm(gz[pp].z + az2);
            float z3 = sigm(gz[pp].w + az3);
            float r0 = sigm(gr[pp].x + ar0);
            float r1 = sigm(gr[pp].y + ar1);
            float r2 = sigm(gr[pp].z + ar2);
            float r3 = sigm(gr[pp].w + ar3);
            float c0 = tanh_fast(gc[pp].x + r0 * ah0);
            float c1 = tanh_fast(gc[pp].y + r1 * ah1);
            float c2 = tanh_fast(gc[pp].z + r2 * ah2);
            float c3 = tanh_fast(gc[pp].w + r3 * ah3);
            float4 hold = *(const float4*)(shH + p * 68 + j0);
            float n0 = z0 * hold.x + (1.0f - z0) * c0;
            float n1 = z1 * hold.y + (1.0f - z1) * c1;
            float n2 = z2 * hold.z + (1.0f - z2) * c2;
            float n3 = z3 * hold.w + (1.0f - z3) * c3;
            *(float4*)(shHn + p * 68 + j0) = make_float4(n0, n1, n2, n3);
            if (SCATTER && pv[pp]) {
                red4(g_m + (size_t)liA[pp] * 64 + j0, n0, n1, n2, n3);
            }
        }
        hbuf ^= 1;
        __syncthreads();
    }

    float* shF = shh + hbuf * 4352;
    #pragma unroll
    for (int r = 0; r < 4; r++) {
        int idx = r * 256 + tid;
        int p = idx >> 4, iq = idx & 15;
        int pglob = pbase + p;
        if (pglob < NP) {
            float4 v = *(const float4*)(shF + p * 68 + iq * 4);
            ((float4*)g_path)[(size_t)pglob * 16 + iq] = v;
        }
    }
}

// ------- z[s][c*32+o] = sum_i node[s][i] * W2[i][c*32+o];  + beta cols ----
__global__ void __launch_bounds__(256) z_kernel(const float* __restrict__ bk, int cur) {
    __shared__ __align__(16) float Ns[512];
    int tid = threadIdx.x;
    int n0 = blockIdx.x * 16;
    const float* nst = g_node[cur];
    for (int r = tid; r < 512; r += 256) {
        int i = r >> 4, nl = r & 15;
        int nn = n0 + nl; if (nn >= NN) nn = NN - 1;
        Ns[r] = nst[(size_t)nn * 32 + i];
    }
    __syncthreads();
    int o = blockIdx.y * 512 + tid;
    ull acc0[8], acc1[8];
    #pragma unroll
    for (int q = 0; q < 8; q++) { acc0[q] = 0ull; acc1[q] = 0ull; }
    for (int i = 0; i < 32; i++) {
        float w0 = g_W2[i * 1024 + o];
        float w1 = g_W2[i * 1024 + o + 256];
        ull w0p = pack2(w0, w0);
        ull w1p = pack2(w1, w1);
        const ulonglong2* np = (const ulonglong2*)(Ns + i * 16);
        #pragma unroll
        for (int q2 = 0; q2 < 4; q2++) {
            ulonglong2 nv = np[q2];
            ffma2(acc0[q2 * 2 + 0], nv.x, w0p);
            ffma2(acc0[q2 * 2 + 1], nv.y, w0p);
            ffma2(acc1[q2 * 2 + 0], nv.x, w1p);
            ffma2(acc1[q2 * 2 + 1], nv.y, w1p);
        }
    }
    #pragma unroll
    for (int q = 0; q < 8; q++) {
        float v0, v1, u0, u1;
        unpack2(acc0[q], v0, v1);
        unpack2(acc1[q], u0, u1);
        int na = n0 + 2 * q, nb = n0 + 2 * q + 1;
        if (na < NN) { g_z[(size_t)na * 1056 + o] = v0; g_z[(size_t)na * 1056 + o + 256] = u0; }
        if (nb < NN) { g_z[(size_t)nb * 1056 + o] = v1; g_z[(size_t)nb * 1056 + o + 256] = u1; }
    }
    if (blockIdx.y == 0) {
        int nl = tid >> 5;
        int oo = tid & 31;
        float b0 = 0.0f, b1 = 0.0f;
        #pragma unroll
        for (int i = 0; i < 32; i++) {
            float bkv = bk[i * 32 + oo];
            b0 += Ns[i * 16 + nl] * bkv;
            b1 += Ns[i * 16 + nl + 8] * bkv;
        }
        if (n0 + nl < NN)     g_z[(size_t)(n0 + nl) * 1056 + 1024 + oo] = b0;
        if (n0 + nl + 8 < NN) g_z[(size_t)(n0 + nl + 8) * 1056 + 1024 + oo] = b1;
    }
}

// --------- root (stores): node1 = broot + node0@wroot ---------------------
__global__ void __launch_bounds__(256) root_kernel(const float* __restrict__ wroot,
                                                   const float* __restrict__ broot,
                                                   int cur, int nxt) {
    __shared__ float sw[1024];
    int tid = threadIdx.x;
    for (int i = tid; i < 1024; i += 256) sw[i] = wroot[i];
    __syncthreads();
    int w = tid >> 5, lane = tid & 31;
    int n = blockIdx.x * 8 + w;
    const float* nr = g_node[cur] + (size_t)n * 32;
    float acc = broot[lane];
    #pragma unroll
    for (int i = 0; i < 32; i++) acc += nr[i] * sw[i * 32 + lane];
    g_node[nxt][(size_t)n * 32 + lane] = acc;
}

// ----- fused edge MLP + ECC message --------------------------------------
__global__ void __launch_bounds__(256) edge_msg_kernel(const int* __restrict__ l2n,
                                                       const int* __restrict__ senders,
                                                       const int* __restrict__ recv,
                                                       int cur, int nxt) {
    __shared__ float sWe[4096];
    __shared__ float sbe[32];
    __shared__ float con[8][128];
    __shared__ float sL[8][32];
    int tid = threadIdx.x;
    for (int i = tid; i < 4096; i += 256) sWe[i] = g_We[i];
    if (tid < 32) sbe[tid] = g_be[tid];
    int w = tid >> 5, lane = tid & 31;
    int l = blockIdx.x * 8 + w;
    int nn = l2n[l];
    con[w][lane]      = g_node[cur][(size_t)nn * 32 + lane];
    con[w][32 + lane] = g_link[cur][(size_t)l * 32 + lane];
    con[w][64 + lane] = g_m[(size_t)l * 64 + lane];
    con[w][96 + lane] = g_m[(size_t)l * 64 + 32 + lane];
    __syncthreads();
    float acc = sbe[lane];
    #pragma unroll
    for (int c = 0; c < 128; c++) acc += con[w][c] * sWe[c * 32 + lane];
    g_link[nxt][(size_t)l * 32 + lane] = acc;
    sL[w][lane] = acc;
    __syncwarp();
    int s = senders[l];
    const float* zr = g_z + (size_t)s * 1056;
    float macc = zr[1024 + lane];
    #pragma unroll
    for (int c = 0; c < 32; c++) macc += sL[w][c] * zr[c * 32 + lane];
    atomicAdd(&g_node[nxt][(size_t)recv[l] * 32 + lane], macc);
}

// ---------------- readout: 32 paths/block (4 per warp) --------------------
__global__ void __launch_bounds__(256) readout_kernel(
    const float* __restrict__ rw1, const float* __restrict__ rb1,
    const float* __restrict__ rw2, const float* __restrict__ rb2,
    const float* __restrict__ fw,  const float* __restrict__ fb,
    float* __restrict__ out) {
    __shared__ float sw1[2048], sw2[1024], sfw[96];
    __shared__ float shp[8][64], sr1[8][33];
    int tid = threadIdx.x, w = tid >> 5, lane = tid & 31;
    for (int i = tid; i < 2048; i += 256) sw1[i] = rw1[i];
    for (int i = tid; i < 1024; i += 256) sw2[i] = rw2[i];
    if (tid < 96) sfw[tid] = fw[tid];
    __syncthreads();
    float rb1l = rb1[lane], rb2l = rb2[lane], fb0 = fb[0];
    #pragma unroll
    for (int it = 0; it < 4; it++) {
        int p = blockIdx.x * 32 + w * 4 + it;
        int pcl = (p < NP) ? p : NP - 1;
        shp[w][lane]      = g_path[(size_t)pcl * 64 + lane];
        shp[w][32 + lane] = g_path[(size_t)pcl * 64 + 32 + lane];
        __syncwarp();
        float acc = rb1l;
        #pragma unroll
        for (int i = 0; i < 64; i++) acc += shp[w][i] * sw1[i * 32 + lane];
        float r1 = selu_f(acc);
        sr1[w][lane] = r1;
        __syncwarp();
        float acc2 = rb2l;
        #pragma unroll
        for (int i = 0; i < 32; i++) acc2 += sr1[w][i] * sw2[i * 32 + lane];
        float r2 = selu_f(acc2);
        float part = r2 * sfw[lane] + shp[w][lane] * sfw[32 + lane]
                   + shp[w][32 + lane] * sfw[64 + lane];
        #pragma unroll
        for (int o = 16; o; o >>= 1) part += __shfl_down_sync(0xffffffffu, part, o);
        if (lane == 0 && p < NP) out[p] = part + fb0;
        __syncwarp();
    }
}

// ---------------------------- launcher ------------------------------------
extern "C" void kernel_launch(void* const* d_in, const int* in_sizes, int n_in,
                              void* d_out, int out_size) {
    const float* link_init = (const float*)d_in[0];
    const float* node_init = (const float*)d_in[1];
    const float* path_init = (const float*)d_in[2];
    const float* gru_wx    = (const float*)d_in[3];
    const float* gru_wh    = (const float*)d_in[4];
    const float* gru_b     = (const float*)d_in[5];
    const float* e_w1      = (const float*)d_in[6];
    const float* e_b1      = (const float*)d_in[7];
    const float* e_w2      = (const float*)d_in[8];
    const float* e_b2      = (const float*)d_in[9];
    const float* ecc_wk    = (const float*)d_in[10];
    const float* ecc_bk    = (const float*)d_in[11];
    const float* ecc_wroot = (const float*)d_in[12];
    const float* ecc_broot = (const float*)d_in[13];
    const float* r_w1      = (const float*)d_in[14];
    const float* r_b1      = (const float*)d_in[15];
    const float* r_w2      = (const float*)d_in[16];
    const float* r_b2      = (const float*)d_in[17];
    const float* f_w       = (const float*)d_in[18];
    const float* f_b       = (const float*)d_in[19];
    const int* l2p   = (const int*)d_in[22];
    const int* n2p   = (const int*)d_in[23];
    const int* l2n   = (const int*)d_in[24];
    const int* senders   = (const int*)d_in[25];
    const int* receivers = (const int*)d_in[26];
    float* out = (float*)d_out;

    cudaFuncSetAttribute((const void*)gru_kernel<1, 1>,
                         cudaFuncAttributeMaxDynamicSharedMemorySize, GRU_SMEM_BYTES);
    cudaFuncSetAttribute((const void*)gru_kernel<0, 0>,
                         cudaFuncAttributeMaxDynamicSharedMemorySize, GRU_SMEM_BYTES);

    prep_all_k<<<193, 256>>>(gru_wh, gru_b, e_w1, e_b1, e_w2, e_b2, ecc_wk);   // 0
    init_all_k<<<20625, 256>>>(link_init, node_init, path_init);               // 1
    lxnx1_kernel<<<3125, 192>>>(gru_wx, gru_b, link_init, node_init);          // 2
    gru_kernel<1, 1><<<782, 256, GRU_SMEM_BYTES>>>(l2p, n2p);                  // 3
    z_kernel<<<dim3(313, 2), 256>>>(ecc_bk, 0);                                // 4
    root_kernel<<<625, 256>>>(ecc_wroot, ecc_broot, 0, 1);                     // 5
    edge_msg_kernel<<<2500, 256>>>(l2n, senders, receivers, 0, 1);             // 6
    lxnx_kernel<<<3125, 192>>>(gru_wx, gru_b, 1);                              // 7
    gru_kernel<0, 0><<<782, 256, GRU_SMEM_BYTES>>>(l2p, n2p);                  // 8
    readout_kernel<<<1563, 256>>>(r_w1, r_b1, r_w2, r_b2, f_w, f_b, out);      // 9
}